// round 15
// baseline (speedup 1.0000x reference)
#include <cuda_runtime.h>
#include <cstdint>
#include <cstddef>

// q,k,v = [2,16,2048,64] fp32.  Output = out [2,16,2048,64] ++ p_attn [2,16,2048,2048] fp32.

namespace {
constexpr int BATCH_HEADS = 32;
constexpr int SEQ   = 2048;
constexpr int DH    = 64;
constexpr int BM    = 128;               // query rows per CTA
constexpr int BN    = 64;                // kv chunk
constexpr int NCHUNK = SEQ / BN;         // 32
constexpr int NT    = BN / 8;            // 8 n-tiles per chunk
constexpr int NTHREADS = 256;            // 8 warps, 16-row band each

constexpr int KSTR  = 80;                // ≡16 mod 32: conflict-free float4 B loads (QK)
constexpr int VTSTR = 72;                // ≡8 mod 32: conflict-free float2 B loads (PV, VT layout)
constexpr int KRSZ = BN * KSTR;          // 5120 floats per K buffer

// pass-1 kernel: 3-deep K ring only -> 61.4 KB -> 3 CTAs/SM
constexpr int P1_SMEM_FLOATS = 3 * KRSZ;            // 15360
// pass-2 kernel: K double buffer + VT double buffer -> 77.8 KB -> 2 CTAs/SM
constexpr int KB0 = 0;
constexpr int KB1 = KRSZ;                // 5120
constexpr int VB0 = 2 * KRSZ;            // 10240
constexpr int VB1 = VB0 + DH * VTSTR;    // 14848
constexpr int P2_SMEM_FLOATS = VB1 + DH * VTSTR;    // 19456

constexpr size_t OUT_ELEMS = (size_t)BATCH_HEADS * SEQ * DH;  // 4194304

// fused prep grid split
constexpr int VT_BLOCKS = BATCH_HEADS * (SEQ / 32) * (DH / 32);   // 4096
constexpr int QK_BLOCKS = 1184;
constexpr int PREP_BLOCKS = VT_BLOCKS + QK_BLOCKS;
}

// scratch (prep kernels fill)
__device__ float g_qs[OUT_ELEMS];   // pre-scaled by 0.125*log2(e), tf32-rounded
__device__ float g_ks[OUT_ELEMS];   // tf32-rounded
__device__ float g_vt[OUT_ELEMS];   // tf32-rounded V, TRANSPOSED per head: [bh][d][s]
__device__ float g_inv[BATCH_HEADS * SEQ];   // per-row softmax-one denominators (pass1 -> pass2)

__device__ __forceinline__ float to_tf32(float x) {
    float r;
    asm("cvt.rna.tf32.f32 %0, %1;" : "=f"(r) : "f"(x));
    return r;
}
__device__ __forceinline__ float ex2f(float x) {
    float r;
    asm("ex2.approx.ftz.f32 %0, %1;" : "=f"(r) : "f"(x));
    return r;
}

__device__ __forceinline__ void mma_tf32(float c[4], float a0, float a1, float a2, float a3,
                                         float b0, float b1) {
    asm volatile(
        "mma.sync.aligned.m16n8k8.row.col.f32.tf32.tf32.f32 "
        "{%0,%1,%2,%3}, {%4,%5,%6,%7}, {%8,%9}, {%0,%1,%2,%3};\n"
        : "+f"(c[0]), "+f"(c[1]), "+f"(c[2]), "+f"(c[3])
        : "r"(__float_as_uint(a0)), "r"(__float_as_uint(a1)),
          "r"(__float_as_uint(a2)), "r"(__float_as_uint(a3)),
          "r"(__float_as_uint(b0)), "r"(__float_as_uint(b1)));
}

__device__ __forceinline__ uint32_t smem_u32(const void* p) {
    uint32_t a;
    asm("{ .reg .u64 t; cvta.to.shared.u64 t, %1; cvt.u32.u64 %0, t; }" : "=r"(a) : "l"(p));
    return a;
}
__device__ __forceinline__ void cpa16(uint32_t dst, const void* src) {
    asm volatile("cp.async.cg.shared.global [%0], [%1], 16;" :: "r"(dst), "l"(src));
}
__device__ __forceinline__ void cpa_commit() {
    asm volatile("cp.async.commit_group;" ::: "memory");
}
template <int N> __device__ __forceinline__ void cpa_wait() {
    asm volatile("cp.async.wait_group %0;" :: "n"(N) : "memory");
}

// ---------------- fused prep: q/k tf32-round + v transpose, one launch ----------------
__global__ __launch_bounds__(256)
void prep_fused_kernel(const float* __restrict__ q,
                       const float* __restrict__ k,
                       const float* __restrict__ v)
{
    __shared__ float tile[32][33];
    if (blockIdx.x < VT_BLOCKS) {
        const int t   = blockIdx.x;
        const int bh  = t >> 7;                 // 128 tiles per head
        const int rem = t & 127;
        const int s0  = (rem >> 1) * 32;
        const int d0  = (rem & 1) * 32;
        const int tx = threadIdx.x & 31;
        const int ty = (threadIdx.x >> 5) * 4;  // 8 warps * 4 rows
        const float* vsrc = v + (size_t)bh * SEQ * DH;
        float* vdst = g_vt + (size_t)bh * SEQ * DH;
        #pragma unroll
        for (int j = 0; j < 4; j++)
            tile[ty + j][tx] = to_tf32(vsrc[(size_t)(s0 + ty + j) * DH + d0 + tx]);
        __syncthreads();
        #pragma unroll
        for (int j = 0; j < 4; j++)
            vdst[(size_t)(d0 + ty + j) * SEQ + s0 + tx] = tile[tx][ty + j];
    } else {
        const int n4 = (int)(OUT_ELEMS / 4);
        const float scale = 0.18033688011112042f;   // (1/8) * log2(e)
        for (int i = (blockIdx.x - VT_BLOCKS) * 256 + threadIdx.x; i < n4;
             i += QK_BLOCKS * 256) {
            float4 t = ((const float4*)q)[i];
            t.x = to_tf32(t.x * scale); t.y = to_tf32(t.y * scale);
            t.z = to_tf32(t.z * scale); t.w = to_tf32(t.w * scale);
            ((float4*)g_qs)[i] = t;
            t = ((const float4*)k)[i];
            t.x = to_tf32(t.x); t.y = to_tf32(t.y); t.z = to_tf32(t.z); t.w = to_tf32(t.w);
            ((float4*)g_ks)[i] = t;
        }
    }
}

// ---------------- PASS 1 kernel: per-row l,m -> g_inv (3 CTAs/SM) ----------------
__global__ __launch_bounds__(NTHREADS, 3)
void sdpa_pass1_kernel()
{
    extern __shared__ float sm[];
    const uint32_t sbase = smem_u32(sm);

    const int bh   = blockIdx.y;
    const int qt   = blockIdx.x;
    const int tid  = threadIdx.x;
    const int w    = tid >> 5;
    const int lane = tid & 31;
    const int r    = lane >> 2;
    const int qd   = lane & 3;

    const size_t hbase = (size_t)bh * SEQ * DH;
    const float* ks = g_ks + hbase;

    const int srow = tid >> 4;
    const int sc4  = tid & 15;

    const int band = w * 16;
    const float* qsrc = g_qs + hbase + (size_t)qt * BM * DH;
    float aQ[4][8];
    #pragma unroll
    for (int kk2 = 0; kk2 < 4; kk2++) {
        float4 t0 = *(const float4*)(qsrc + (band + r) * DH + kk2 * 16 + 4 * qd);
        float4 t1 = *(const float4*)(qsrc + (band + r + 8) * DH + kk2 * 16 + 4 * qd);
        aQ[kk2][0] = t0.x; aQ[kk2][1] = t1.x; aQ[kk2][2] = t0.y; aQ[kk2][3] = t1.y;
        aQ[kk2][4] = t0.z; aQ[kk2][5] = t1.z; aQ[kk2][6] = t0.w; aQ[kk2][7] = t1.w;
    }

    float l0a = 0.f, l0b = 0.f, l1a = 0.f, l1b = 0.f;
    float m0 = -1e30f, m1 = -1e30f;

    #pragma unroll
    for (int pre = 0; pre < 2; pre++) {
        const float* src = ks + (size_t)pre * BN * DH;
        const int kb = pre * KRSZ;
        #pragma unroll
        for (int j = 0; j < 4; j++)
            cpa16(sbase + (uint32_t)((kb + (srow + j * 16) * KSTR + sc4 * 4) * 4),
                  src + (srow + j * 16) * DH + sc4 * 4);
        cpa_commit();
    }
    for (int ch = 0; ch < NCHUNK; ch++) {
        if (ch + 1 < NCHUNK) cpa_wait<1>(); else cpa_wait<0>();
        __syncthreads();
        if (ch + 2 < NCHUNK) {
            const float* src = ks + (size_t)(ch + 2) * BN * DH;
            const int kb = ((ch + 2) % 3) * KRSZ;
            #pragma unroll
            for (int j = 0; j < 4; j++)
                cpa16(sbase + (uint32_t)((kb + (srow + j * 16) * KSTR + sc4 * 4) * 4),
                      src + (srow + j * 16) * DH + sc4 * 4);
            cpa_commit();
        }

        const float* kbuf = sm + (ch % 3) * KRSZ;
        #pragma unroll 2
        for (int nt = 0; nt < NT; nt++) {
            float ca[4] = {0.f, 0.f, 0.f, 0.f};
            float cb[4] = {0.f, 0.f, 0.f, 0.f};
            const float* kb = kbuf + (nt * 8 + r) * KSTR + 4 * qd;
            #pragma unroll
            for (int kk2 = 0; kk2 < 4; kk2++) {
                float4 b = *(const float4*)(kb + kk2 * 16);
                mma_tf32(ca, aQ[kk2][0], aQ[kk2][1], aQ[kk2][2], aQ[kk2][3], b.x, b.y);
                mma_tf32(cb, aQ[kk2][4], aQ[kk2][5], aQ[kk2][6], aQ[kk2][7], b.z, b.w);
            }
            float s0 = ca[0] + cb[0], s1 = ca[1] + cb[1];
            float s2 = ca[2] + cb[2], s3 = ca[3] + cb[3];
            m0 = fmaxf(m0, fmaxf(s0, s1));
            m1 = fmaxf(m1, fmaxf(s2, s3));
            l0a += ex2f(s0);
            l0b += ex2f(s1);
            l1a += ex2f(s2);
            l1b += ex2f(s3);
        }
    }

    float l0 = l0a + l0b, l1 = l1a + l1b;
    #pragma unroll
    for (int off = 1; off <= 2; off <<= 1) {
        l0 += __shfl_xor_sync(0xffffffffu, l0, off);
        l1 += __shfl_xor_sync(0xffffffffu, l1, off);
        m0 = fmaxf(m0, __shfl_xor_sync(0xffffffffu, m0, off));
        m1 = fmaxf(m1, __shfl_xor_sync(0xffffffffu, m1, off));
    }
    // softmax-one: p_i = 2^{c_i - m} / (1 + sum 2^{c_j - m}) = 2^{c_i} / (2^m + l)
    if (qd == 0) {
        const int rowbase = bh * SEQ + qt * BM + band + r;
        g_inv[rowbase]     = 1.f / (ex2f(m0) + l0);
        g_inv[rowbase + 8] = 1.f / (ex2f(m1) + l1);
    }
}

// ---------------- PASS 2 kernel: recompute S, write p, O += P @ V (2 CTAs/SM) ----------------
__global__ __launch_bounds__(NTHREADS, 2)
void sdpa_pass2_kernel(float* __restrict__ out, float* __restrict__ p)
{
    extern __shared__ float sm[];
    const uint32_t sbase = smem_u32(sm);

    const int bh   = blockIdx.y;
    const int qt   = blockIdx.x;
    const int tid  = threadIdx.x;
    const int w    = tid >> 5;
    const int lane = tid & 31;
    const int r    = lane >> 2;
    const int qd   = lane & 3;

    const size_t hbase = (size_t)bh * SEQ * DH;
    const float* ks = g_ks + hbase;
    const float* vt = g_vt + hbase;               // [d][s] layout
    float* og = out + hbase + (size_t)qt * BM * DH;
    float* pg = p + (size_t)bh * SEQ * SEQ + (size_t)qt * BM * SEQ;

    const int srow = tid >> 4;
    const int sc4  = tid & 15;

    const int band = w * 16;
    const float* qsrc = g_qs + hbase + (size_t)qt * BM * DH;
    float aQ[4][8];
    #pragma unroll
    for (int kk2 = 0; kk2 < 4; kk2++) {
        float4 t0 = *(const float4*)(qsrc + (band + r) * DH + kk2 * 16 + 4 * qd);
        float4 t1 = *(const float4*)(qsrc + (band + r + 8) * DH + kk2 * 16 + 4 * qd);
        aQ[kk2][0] = t0.x; aQ[kk2][1] = t1.x; aQ[kk2][2] = t0.y; aQ[kk2][3] = t1.y;
        aQ[kk2][4] = t0.z; aQ[kk2][5] = t1.z; aQ[kk2][6] = t0.w; aQ[kk2][7] = t1.w;
    }

    const int rowbase = bh * SEQ + qt * BM + band + r;
    const float inv0 = g_inv[rowbase];
    const float inv1 = g_inv[rowbase + 8];

    float acc[8][4];
    #pragma unroll
    for (int no = 0; no < 8; no++) {
        acc[no][0] = 0.f; acc[no][1] = 0.f; acc[no][2] = 0.f; acc[no][3] = 0.f;
    }

    {
        #pragma unroll
        for (int j = 0; j < 4; j++) {
            cpa16(sbase + (uint32_t)((KB0 + (srow + j * 16) * KSTR + sc4 * 4) * 4),
                  ks + (srow + j * 16) * DH + sc4 * 4);
            cpa16(sbase + (uint32_t)((VB0 + (srow + j * 16) * VTSTR + sc4 * 4) * 4),
                  vt + (size_t)(srow + j * 16) * SEQ + sc4 * 4);
        }
        cpa_commit();
    }
    for (int ch = 0; ch < NCHUNK; ch++) {
        if (ch > 0) __syncthreads();
        if (ch + 1 < NCHUNK) {
            const int kb = ((ch + 1) & 1) ? KB1 : KB0;
            const int vb = ((ch + 1) & 1) ? VB1 : VB0;
            const float* srck = ks + (size_t)(ch + 1) * BN * DH;
            const float* srcv = vt + (ch + 1) * BN;
            #pragma unroll
            for (int j = 0; j < 4; j++) {
                cpa16(sbase + (uint32_t)((kb + (srow + j * 16) * KSTR + sc4 * 4) * 4),
                      srck + (srow + j * 16) * DH + sc4 * 4);
                cpa16(sbase + (uint32_t)((vb + (srow + j * 16) * VTSTR + sc4 * 4) * 4),
                      srcv + (size_t)(srow + j * 16) * SEQ + sc4 * 4);
            }
            cpa_commit();
            cpa_wait<1>();
        } else {
            cpa_wait<0>();
        }
        __syncthreads();

        const float* kbuf  = sm + ((ch & 1) ? KB1 : KB0);
        const float* vtbuf = sm + ((ch & 1) ? VB1 : VB0);
        float* prow0 = pg + (size_t)(band + r) * SEQ + ch * BN + 2 * qd;
        float* prow1 = pg + (size_t)(band + r + 8) * SEQ + ch * BN + 2 * qd;

        #pragma unroll 1
        for (int nt = 0; nt < NT; nt++) {
            float ca[4] = {0.f, 0.f, 0.f, 0.f};
            float cb[4] = {0.f, 0.f, 0.f, 0.f};
            const float* kb = kbuf + (nt * 8 + r) * KSTR + 4 * qd;
            #pragma unroll
            for (int kk2 = 0; kk2 < 4; kk2++) {
                float4 b = *(const float4*)(kb + kk2 * 16);
                mma_tf32(ca, aQ[kk2][0], aQ[kk2][1], aQ[kk2][2], aQ[kk2][3], b.x, b.y);
                mma_tf32(cb, aQ[kk2][4], aQ[kk2][5], aQ[kk2][6], aQ[kk2][7], b.z, b.w);
            }
            float p0 = to_tf32(ex2f(ca[0] + cb[0]) * inv0);
            float p1 = to_tf32(ex2f(ca[1] + cb[1]) * inv0);
            float p2 = to_tf32(ex2f(ca[2] + cb[2]) * inv1);
            float p3 = to_tf32(ex2f(ca[3] + cb[3]) * inv1);

            *(float2*)(prow0 + nt * 8) = make_float2(p0, p1);
            *(float2*)(prow1 + nt * 8) = make_float2(p2, p3);

            // O += P_tile @ V_rows; VT layout -> B pair is one LDS.64
            const float* vrow = vtbuf + nt * 8 + 2 * qd + r * VTSTR;
            #pragma unroll
            for (int no = 0; no < 8; no++) {
                float2 b = *(const float2*)(vrow + no * 8 * VTSTR);
                mma_tf32(acc[no], p0, p2, p1, p3, b.x, b.y);
            }
        }
    }

    #pragma unroll
    for (int no = 0; no < 8; no++) {
        *(float2*)(og + (size_t)(band + r) * DH + no * 8 + 2 * qd) =
            make_float2(acc[no][0], acc[no][1]);
        *(float2*)(og + (size_t)(band + r + 8) * DH + no * 8 + 2 * qd) =
            make_float2(acc[no][2], acc[no][3]);
    }
}

extern "C" void kernel_launch(void* const* d_in, const int* in_sizes, int n_in,
                              void* d_out, int out_size)
{
    const float* q = (const float*)d_in[0];
    const float* k = (const float*)d_in[1];
    const float* v = (const float*)d_in[2];
    float* out = (float*)d_out;
    float* p   = (float*)d_out + OUT_ELEMS;

    (void)in_sizes; (void)n_in; (void)out_size;

    prep_fused_kernel<<<PREP_BLOCKS, 256>>>(q, k, v);

    cudaFuncSetAttribute(sdpa_pass1_kernel,
                         cudaFuncAttributeMaxDynamicSharedMemorySize,
                         P1_SMEM_FLOATS * sizeof(float));
    cudaFuncSetAttribute(sdpa_pass2_kernel,
                         cudaFuncAttributeMaxDynamicSharedMemorySize,
                         P2_SMEM_FLOATS * sizeof(float));

    dim3 grid(SEQ / BM, BATCH_HEADS);   // (16, 32)
    sdpa_pass1_kernel<<<grid, NTHREADS, P1_SMEM_FLOATS * sizeof(float)>>>();
    sdpa_pass2_kernel<<<grid, NTHREADS, P2_SMEM_FLOATS * sizeof(float)>>>(out, p);
}

// round 16
// speedup vs baseline: 1.0330x; 1.0330x over previous
#include <cuda_runtime.h>
#include <cstdint>
#include <cstddef>

// q,k,v = [2,16,2048,64] fp32.  Output = out [2,16,2048,64] ++ p_attn [2,16,2048,2048] fp32.

namespace {
constexpr int BATCH_HEADS = 32;
constexpr int SEQ   = 2048;
constexpr int DH    = 64;
constexpr int BM    = 128;               // query rows per CTA
constexpr int BN    = 64;                // kv chunk
constexpr int NCHUNK = SEQ / BN;         // 32
constexpr int NT    = BN / 8;            // 8 n-tiles per chunk
constexpr int NTHREADS = 256;            // 8 warps, 16-row band each

constexpr int KSTR  = 80;                // ≡16 mod 32: conflict-free float4 B loads (QK)
constexpr int VTSTR = 72;                // ≡8 mod 32: conflict-free float2 B loads (PV, VT layout)
constexpr int KRSZ = BN * KSTR;          // 5120 floats per K buffer
// pass 2 layout: K double buffer + VT double buffer
constexpr int KB0 = 0;
constexpr int KB1 = KRSZ;                // 5120
constexpr int VB0 = 2 * KRSZ;            // 10240
constexpr int VB1 = VB0 + DH * VTSTR;    // 14848
constexpr int SMEM_FLOATS = VB1 + DH * VTSTR;  // 19456 floats = 77824 B -> 2 CTAs/SM
// pass 1 reuses [0, 3*KRSZ) = 15360 floats as a 3-deep K ring
static_assert(3 * KRSZ <= SMEM_FLOATS, "pass-1 ring must fit");

constexpr size_t OUT_ELEMS = (size_t)BATCH_HEADS * SEQ * DH;  // 4194304

// prep grid split: v-transpose tiles + k-round blocks
constexpr int VT_BLOCKS = BATCH_HEADS * (SEQ / 32) * (DH / 32);   // 4096
constexpr int KR_BLOCKS = 1184;
constexpr int PREP_BLOCKS = VT_BLOCKS + KR_BLOCKS;

constexpr float SCALE_L2E = 0.18033688011112042f;   // (1/8) * log2(e)
}

// tf32-rounded scratch (prep kernel fills); Q is rounded inline in the main kernel
__device__ float g_ks[OUT_ELEMS];   // tf32-rounded K
__device__ float g_vt[OUT_ELEMS];   // tf32-rounded V, TRANSPOSED per head: [bh][d][s]

__device__ __forceinline__ float to_tf32(float x) {
    float r;
    asm("cvt.rna.tf32.f32 %0, %1;" : "=f"(r) : "f"(x));
    return r;
}
__device__ __forceinline__ float ex2f(float x) {
    float r;
    asm("ex2.approx.ftz.f32 %0, %1;" : "=f"(r) : "f"(x));
    return r;
}
__device__ __forceinline__ float lg2f(float x) {
    float r;
    asm("lg2.approx.ftz.f32 %0, %1;" : "=f"(r) : "f"(x));
    return r;
}

__device__ __forceinline__ void mma_tf32(float c[4], float a0, float a1, float a2, float a3,
                                         float b0, float b1) {
    asm volatile(
        "mma.sync.aligned.m16n8k8.row.col.f32.tf32.tf32.f32 "
        "{%0,%1,%2,%3}, {%4,%5,%6,%7}, {%8,%9}, {%0,%1,%2,%3};\n"
        : "+f"(c[0]), "+f"(c[1]), "+f"(c[2]), "+f"(c[3])
        : "r"(__float_as_uint(a0)), "r"(__float_as_uint(a1)),
          "r"(__float_as_uint(a2)), "r"(__float_as_uint(a3)),
          "r"(__float_as_uint(b0)), "r"(__float_as_uint(b1)));
}

__device__ __forceinline__ uint32_t smem_u32(const void* p) {
    uint32_t a;
    asm("{ .reg .u64 t; cvta.to.shared.u64 t, %1; cvt.u32.u64 %0, t; }" : "=r"(a) : "l"(p));
    return a;
}
__device__ __forceinline__ void cpa16(uint32_t dst, const void* src) {
    asm volatile("cp.async.cg.shared.global [%0], [%1], 16;" :: "r"(dst), "l"(src));
}
__device__ __forceinline__ void cpa_commit() {
    asm volatile("cp.async.commit_group;" ::: "memory");
}
template <int N> __device__ __forceinline__ void cpa_wait() {
    asm volatile("cp.async.wait_group %0;" :: "n"(N) : "memory");
}

// ---------------- prep: k tf32-round + v transpose ----------------
__global__ __launch_bounds__(256)
void prep_kernel(const float* __restrict__ k, const float* __restrict__ v)
{
    __shared__ float tile[32][33];
    if (blockIdx.x < VT_BLOCKS) {
        // transpose-v path: g_vt[bh][d][s] = tf32(v[bh][s][d])
        const int t   = blockIdx.x;
        const int bh  = t >> 7;                 // 128 tiles per head
        const int rem = t & 127;
        const int s0  = (rem >> 1) * 32;
        const int d0  = (rem & 1) * 32;
        const int tx = threadIdx.x & 31;
        const int ty = (threadIdx.x >> 5) * 4;  // 8 warps * 4 rows
        const float* vsrc = v + (size_t)bh * SEQ * DH;
        float* vdst = g_vt + (size_t)bh * SEQ * DH;
        #pragma unroll
        for (int j = 0; j < 4; j++)
            tile[ty + j][tx] = to_tf32(vsrc[(size_t)(s0 + ty + j) * DH + d0 + tx]);
        __syncthreads();
        #pragma unroll
        for (int j = 0; j < 4; j++)
            vdst[(size_t)(d0 + ty + j) * SEQ + s0 + tx] = tile[tx][ty + j];
    } else {
        const int n4 = (int)(OUT_ELEMS / 4);
        for (int i = (blockIdx.x - VT_BLOCKS) * 256 + threadIdx.x; i < n4;
             i += KR_BLOCKS * 256) {
            float4 t = ((const float4*)k)[i];
            t.x = to_tf32(t.x); t.y = to_tf32(t.y); t.z = to_tf32(t.z); t.w = to_tf32(t.w);
            ((float4*)g_ks)[i] = t;
        }
    }
}

// ---------------- main kernel ----------------
__global__ __launch_bounds__(NTHREADS, 2)
void sdpa_softmax1_kernel(const float* __restrict__ q,
                          float* __restrict__ out, float* __restrict__ p)
{
    extern __shared__ float sm[];
    const uint32_t sbase = smem_u32(sm);

    const int bh   = blockIdx.y;
    const int qt   = blockIdx.x;
    const int tid  = threadIdx.x;
    const int w    = tid >> 5;
    const int lane = tid & 31;
    const int r    = lane >> 2;   // groupID 0..7
    const int qd   = lane & 3;    // threadID_in_group 0..3

    const size_t hbase = (size_t)bh * SEQ * DH;
    const float* ks = g_ks + hbase;
    const float* vt = g_vt + hbase;               // [d][s] layout
    float* og = out + hbase + (size_t)qt * BM * DH;
    float* pg = p + (size_t)bh * SEQ * SEQ + (size_t)qt * BM * SEQ;

    // staging split: per thread 4 cp.async of 16B per 64x64 tile
    const int srow = tid >> 4;        // 0..15; rows srow + j*16, j<4
    const int sc4  = tid & 15;        // 16B column chunk

    // ---- preload Q A-fragments straight from q (scale*log2e + tf32 inline) ----
    const int band = w * 16;
    const float* qsrc = q + hbase + (size_t)qt * BM * DH;
    float aQ[4][8];
    #pragma unroll
    for (int kk2 = 0; kk2 < 4; kk2++) {
        float4 t0 = *(const float4*)(qsrc + (band + r) * DH + kk2 * 16 + 4 * qd);
        float4 t1 = *(const float4*)(qsrc + (band + r + 8) * DH + kk2 * 16 + 4 * qd);
        aQ[kk2][0] = to_tf32(t0.x * SCALE_L2E); aQ[kk2][1] = to_tf32(t1.x * SCALE_L2E);
        aQ[kk2][2] = to_tf32(t0.y * SCALE_L2E); aQ[kk2][3] = to_tf32(t1.y * SCALE_L2E);
        aQ[kk2][4] = to_tf32(t0.z * SCALE_L2E); aQ[kk2][5] = to_tf32(t1.z * SCALE_L2E);
        aQ[kk2][6] = to_tf32(t0.w * SCALE_L2E); aQ[kk2][7] = to_tf32(t1.w * SCALE_L2E);
    }

    float l0a = 0.f, l0b = 0.f, l1a = 0.f, l1b = 0.f;
    float m0 = -1e30f, m1 = -1e30f;

    // ================= PASS 1: row sums + max (3-deep K ring, 1 sync/chunk) =================
    #pragma unroll
    for (int pre = 0; pre < 2; pre++) {
        const float* src = ks + (size_t)pre * BN * DH;
        const int kb = pre * KRSZ;
        #pragma unroll
        for (int j = 0; j < 4; j++)
            cpa16(sbase + (uint32_t)((kb + (srow + j * 16) * KSTR + sc4 * 4) * 4),
                  src + (srow + j * 16) * DH + sc4 * 4);
        cpa_commit();
    }
    for (int ch = 0; ch < NCHUNK; ch++) {
        if (ch + 1 < NCHUNK) cpa_wait<1>(); else cpa_wait<0>();
        __syncthreads();   // stage(ch) visible; compute(ch-1) globally done
        if (ch + 2 < NCHUNK) {
            const float* src = ks + (size_t)(ch + 2) * BN * DH;
            const int kb = ((ch + 2) % 3) * KRSZ;
            #pragma unroll
            for (int j = 0; j < 4; j++)
                cpa16(sbase + (uint32_t)((kb + (srow + j * 16) * KSTR + sc4 * 4) * 4),
                      src + (srow + j * 16) * DH + sc4 * 4);
            cpa_commit();
        }

        const float* kbuf = sm + (ch % 3) * KRSZ;
        #pragma unroll 2
        for (int nt = 0; nt < NT; nt++) {
            float ca[4] = {0.f, 0.f, 0.f, 0.f};
            float cb[4] = {0.f, 0.f, 0.f, 0.f};
            const float* kb = kbuf + (nt * 8 + r) * KSTR + 4 * qd;
            #pragma unroll
            for (int kk2 = 0; kk2 < 4; kk2++) {
                float4 b = *(const float4*)(kb + kk2 * 16);
                mma_tf32(ca, aQ[kk2][0], aQ[kk2][1], aQ[kk2][2], aQ[kk2][3], b.x, b.y);
                mma_tf32(cb, aQ[kk2][4], aQ[kk2][5], aQ[kk2][6], aQ[kk2][7], b.z, b.w);
            }
            float s0 = ca[0] + cb[0], s1 = ca[1] + cb[1];
            float s2 = ca[2] + cb[2], s3 = ca[3] + cb[3];
            m0 = fmaxf(m0, fmaxf(s0, s1));
            m1 = fmaxf(m1, fmaxf(s2, s3));
            l0a += ex2f(s0);
            l0b += ex2f(s1);
            l1a += ex2f(s2);
            l1b += ex2f(s3);
        }
    }

    float l0 = l0a + l0b, l1 = l1a + l1b;
    #pragma unroll
    for (int off = 1; off <= 2; off <<= 1) {
        l0 += __shfl_xor_sync(0xffffffffu, l0, off);
        l1 += __shfl_xor_sync(0xffffffffu, l1, off);
        m0 = fmaxf(m0, __shfl_xor_sync(0xffffffffu, m0, off));
        m1 = fmaxf(m1, __shfl_xor_sync(0xffffffffu, m1, off));
    }
    // softmax-one: p_i = 2^{c_i}/(2^m + l) = 2^{c_i + linv},  linv = -log2(2^m + l)
    const float linv0 = -lg2f(ex2f(m0) + l0);
    const float linv1 = -lg2f(ex2f(m1) + l1);

    float acc[8][4];
    #pragma unroll
    for (int no = 0; no < 8; no++) {
        acc[no][0] = 0.f; acc[no][1] = 0.f; acc[no][2] = 0.f; acc[no][3] = 0.f;
    }

    // ================= PASS 2: recompute S, write p, O += P @ V =================
    __syncthreads();   // pass-1 reads done before restaging shared buffers
    {
        #pragma unroll
        for (int j = 0; j < 4; j++) {
            cpa16(sbase + (uint32_t)((KB0 + (srow + j * 16) * KSTR + sc4 * 4) * 4),
                  ks + (srow + j * 16) * DH + sc4 * 4);
            cpa16(sbase + (uint32_t)((VB0 + (srow + j * 16) * VTSTR + sc4 * 4) * 4),
                  vt + (size_t)(srow + j * 16) * SEQ + sc4 * 4);
        }
        cpa_commit();
    }
    for (int ch = 0; ch < NCHUNK; ch++) {
        if (ch > 0) __syncthreads();
        if (ch + 1 < NCHUNK) {
            const int kb = ((ch + 1) & 1) ? KB1 : KB0;
            const int vb = ((ch + 1) & 1) ? VB1 : VB0;
            const float* srck = ks + (size_t)(ch + 1) * BN * DH;
            const float* srcv = vt + (ch + 1) * BN;
            #pragma unroll
            for (int j = 0; j < 4; j++) {
                cpa16(sbase + (uint32_t)((kb + (srow + j * 16) * KSTR + sc4 * 4) * 4),
                      srck + (srow + j * 16) * DH + sc4 * 4);
                cpa16(sbase + (uint32_t)((vb + (srow + j * 16) * VTSTR + sc4 * 4) * 4),
                      srcv + (size_t)(srow + j * 16) * SEQ + sc4 * 4);
            }
            cpa_commit();
            cpa_wait<1>();
        } else {
            cpa_wait<0>();
        }
        __syncthreads();

        const float* kbuf  = sm + ((ch & 1) ? KB1 : KB0);
        const float* vtbuf = sm + ((ch & 1) ? VB1 : VB0);
        float* prow0 = pg + (size_t)(band + r) * SEQ + ch * BN + 2 * qd;
        float* prow1 = pg + (size_t)(band + r + 8) * SEQ + ch * BN + 2 * qd;

        #pragma unroll 1
        for (int nt = 0; nt < NT; nt++) {
            float ca[4] = {0.f, 0.f, 0.f, 0.f};
            float cb[4] = {0.f, 0.f, 0.f, 0.f};
            const float* kb = kbuf + (nt * 8 + r) * KSTR + 4 * qd;
            #pragma unroll
            for (int kk2 = 0; kk2 < 4; kk2++) {
                float4 b = *(const float4*)(kb + kk2 * 16);
                mma_tf32(ca, aQ[kk2][0], aQ[kk2][1], aQ[kk2][2], aQ[kk2][3], b.x, b.y);
                mma_tf32(cb, aQ[kk2][4], aQ[kk2][5], aQ[kk2][6], aQ[kk2][7], b.z, b.w);
            }
            // p = 2^(c + linv): inv folded into the exponent (saves a FMUL per element)
            float p0 = to_tf32(ex2f(ca[0] + cb[0] + linv0));
            float p1 = to_tf32(ex2f(ca[1] + cb[1] + linv0));
            float p2 = to_tf32(ex2f(ca[2] + cb[2] + linv1));
            float p3 = to_tf32(ex2f(ca[3] + cb[3] + linv1));

            *(float2*)(prow0 + nt * 8) = make_float2(p0, p1);
            *(float2*)(prow1 + nt * 8) = make_float2(p2, p3);

            // O += P_tile @ V_rows; VT layout -> B pair is one LDS.64
            const float* vrow = vtbuf + nt * 8 + 2 * qd + r * VTSTR;
            #pragma unroll
            for (int no = 0; no < 8; no++) {
                float2 b = *(const float2*)(vrow + no * 8 * VTSTR);
                mma_tf32(acc[no], p0, p2, p1, p3, b.x, b.y);
            }
        }
    }

    // ---- epilogue: write out band ----
    #pragma unroll
    for (int no = 0; no < 8; no++) {
        *(float2*)(og + (size_t)(band + r) * DH + no * 8 + 2 * qd) =
            make_float2(acc[no][0], acc[no][1]);
        *(float2*)(og + (size_t)(band + r + 8) * DH + no * 8 + 2 * qd) =
            make_float2(acc[no][2], acc[no][3]);
    }
}

extern "C" void kernel_launch(void* const* d_in, const int* in_sizes, int n_in,
                              void* d_out, int out_size)
{
    const float* q = (const float*)d_in[0];
    const float* k = (const float*)d_in[1];
    const float* v = (const float*)d_in[2];
    float* out = (float*)d_out;
    float* p   = (float*)d_out + OUT_ELEMS;

    (void)in_sizes; (void)n_in; (void)out_size;

    prep_kernel<<<PREP_BLOCKS, 256>>>(k, v);

    cudaFuncSetAttribute(sdpa_softmax1_kernel,
                         cudaFuncAttributeMaxDynamicSharedMemorySize,
                         SMEM_FLOATS * sizeof(float));
    dim3 grid(SEQ / BM, BATCH_HEADS);   // (16, 32)
    sdpa_softmax1_kernel<<<grid, NTHREADS, SMEM_FLOATS * sizeof(float)>>>(q, out, p);
}